// round 8
// baseline (speedup 1.0000x reference)
#include <cuda_runtime.h>
#include <cstdint>

// Problem constants (fixed by setup_inputs): B=32, C=64, n=128, m=128, P=4.

// ---------------------------------------------------------------------------
// JAX partitionable threefry stream, key = jax.random.key(42) -> (k1,k2)=(0,42).
// Element i: (o0,o1) = threefry2x32((0,42), (i>>32, i&0xffffffff)) ; bits = o0^o1
// ---------------------------------------------------------------------------
__device__ __forceinline__ uint32_t threefry_bits(uint32_t i) {
    const uint32_t ks0 = 0u;
    const uint32_t ks1 = 42u;
    const uint32_t ks2 = 0x1BD11BDAu ^ ks0 ^ ks1;   // 0x1BD11BF0
    uint32_t x0 = 0u + ks0;      // counter hi word + ks0
    uint32_t x1 = i  + ks1;      // counter lo word + ks1
#define TF_RND(r) { x0 += x1; x1 = __funnelshift_l(x1, x1, (r)); x1 ^= x0; }
    TF_RND(13) TF_RND(15) TF_RND(26) TF_RND(6)
    x0 += ks1; x1 += ks2 + 1u;
    TF_RND(17) TF_RND(29) TF_RND(16) TF_RND(24)
    x0 += ks2; x1 += ks0 + 2u;
    TF_RND(13) TF_RND(15) TF_RND(26) TF_RND(6)
    x0 += ks0; x1 += ks1 + 3u;
    TF_RND(17) TF_RND(29) TF_RND(16) TF_RND(24)
    x0 += ks1; x1 += ks2 + 4u;
    TF_RND(13) TF_RND(15) TF_RND(26) TF_RND(6)
    x0 += ks2; x1 += ks0 + 5u;
#undef TF_RND
    return x0 ^ x1;
}

// JAX uniform(minval=tiny, maxval=1) + gumbel, reproduced op-for-op in f32.
__device__ __forceinline__ float bits_to_gumbel(uint32_t b) {
    const float tiny = 1.17549435e-38f;            // jnp.finfo(f32).tiny
    float f = __uint_as_float((b >> 9) | 0x3f800000u) - 1.0f;  // [0,1)
    float u = fmaxf(tiny, f + tiny);               // (1 - tiny) == 1.0f exactly
    return -logf(-logf(u));
}

// 256-bit streaming store (sm_100+): one dense 32B sector per thread.
__device__ __forceinline__ void stg256_cs(float* p, float4 a, float4 b) {
    asm volatile("st.global.cs.v8.f32 [%0], {%1,%2,%3,%4,%5,%6,%7,%8};"
                 :: "l"(p),
                    "f"(a.x), "f"(a.y), "f"(a.z), "f"(a.w),
                    "f"(b.x), "f"(b.y), "f"(b.z), "f"(b.w)
                 : "memory");
}

// Scatter one s-float4 into two dense 8-float output rows and store.
__device__ __forceinline__ void scatter_store(float* out_row0, float4 sv, uchar4 z) {
    float4 r0a, r0b, r1a, r1b;
    r0a.x = (z.x == 0) ? sv.x : 0.0f;  r0a.y = (z.x == 1) ? sv.x : 0.0f;
    r0a.z = (z.y == 0) ? sv.y : 0.0f;  r0a.w = (z.y == 1) ? sv.y : 0.0f;
    r0b.x = (z.z == 0) ? sv.z : 0.0f;  r0b.y = (z.z == 1) ? sv.z : 0.0f;
    r0b.z = (z.w == 0) ? sv.w : 0.0f;  r0b.w = (z.w == 1) ? sv.w : 0.0f;
    r1a.x = (z.x == 2) ? sv.x : 0.0f;  r1a.y = (z.x == 3) ? sv.x : 0.0f;
    r1a.z = (z.y == 2) ? sv.y : 0.0f;  r1a.w = (z.y == 3) ? sv.y : 0.0f;
    r1b.x = (z.z == 2) ? sv.z : 0.0f;  r1b.y = (z.z == 3) ? sv.z : 0.0f;
    r1b.z = (z.w == 2) ? sv.w : 0.0f;  r1b.w = (z.w == 3) ? sv.w : 0.0f;
    stg256_cs(out_row0,        r0a, r0b);          // row 2i
    stg256_cs(out_row0 + 256u, r1a, r1b);          // row 2i+1
}

// ---------------------------------------------------------------------------
// Fused kernel. One block per (c, i) tile:
//   stage 1: 256 threads compute the 512 gumbel-perturbed scores for the
//            tile's 128 eta rows (2 each) into smem, argmax -> zeta[128].
//   stage 2: stream all 32 batch slices; depth-2 load pipeline balanced
//            against occupancy (5 blocks/SM via launch_bounds reg cap).
// ---------------------------------------------------------------------------
__global__ void __launch_bounds__(256, 5) fused_unpool_kernel(
        const float* __restrict__ etas,
        const float* __restrict__ s,
        float* __restrict__ out) {
    __shared__ float vals[128][5];                 // pad 5: conflict-free argmax
    __shared__ __align__(4) unsigned char zsm[128];

    const unsigned c = blockIdx.x >> 7;            // 0..63
    const unsigned i = blockIdx.x & 127u;          // 0..127
    const unsigned t = threadIdx.x;

    // ---- stage 1: sample zeta for the 128 rows r = (i*128+j)*64 + c ----
#pragma unroll
    for (int h = 0; h < 2; ++h) {
        unsigned q = t + (unsigned)h * 256u;       // q = j*4 + p, q < 512
        unsigned j = q >> 2;
        unsigned p = q & 3u;
        unsigned ctr = 4u * ((i * 128u + j) * 64u + c) + p;
        uint32_t b = threefry_bits(ctr);
        float e = __ldg(etas + ctr);               // etas[r][p] == etas[4r+p]
        vals[j][p] = logf(fmaxf(e, 1e-30f)) + bits_to_gumbel(b);
    }
    __syncthreads();
    if (t < 128u) {                                // first-max argmax (jnp.argmax)
        float v0 = vals[t][0], v1 = vals[t][1], v2 = vals[t][2], v3 = vals[t][3];
        int zi = 0; float zv = v0;
        if (v1 > zv) { zv = v1; zi = 1; }
        if (v2 > zv) { zv = v2; zi = 2; }
        if (v3 > zv) { zv = v3; zi = 3; }
        zsm[t] = (unsigned char)zi;
    }
    __syncthreads();

    // ---- stage 2: scatter all 32 batch slices (depth-2 load pipeline) ----
    const unsigned j4 = t & 31u;                   // 4-j group 0..31
    const unsigned bl = t >> 5;                    // 0..7
    const uchar4 z = *(const uchar4*)&zsm[j4 << 2];

    // b = bo*8 + bl, bo = 0..3. Per-bo strides: bc += 8*64 -> s += 8*64*16384,
    // out += 8*64*65536.
    const float* sp = s   + (((bl * 64u + c) * 128u + i) * 128u) + (j4 << 2);
    float*       op = out + ((bl * 64u + c) * 256u + 2u * i) * 256u + (j4 << 3);
    const unsigned S_STRIDE = 8u * 64u * 16384u;
    const unsigned O_STRIDE = 8u * 64u * 65536u;

    float4 sv0 = __ldcs((const float4*)(sp));
    float4 sv1 = __ldcs((const float4*)(sp + S_STRIDE));
    scatter_store(op, sv0, z);
    float4 sv2 = __ldcs((const float4*)(sp + 2u * S_STRIDE));
    scatter_store(op + O_STRIDE, sv1, z);
    float4 sv3 = __ldcs((const float4*)(sp + 3u * S_STRIDE));
    scatter_store(op + 2u * O_STRIDE, sv2, z);
    scatter_store(op + 3u * O_STRIDE, sv3, z);
}

extern "C" void kernel_launch(void* const* d_in, const int* in_sizes, int n_in,
                              void* d_out, int out_size) {
    // s has 33,554,432 elems; etas 4,194,304. Select by size for robustness.
    const float* s;
    const float* etas;
    if (in_sizes[0] == 33554432) { s = (const float*)d_in[0]; etas = (const float*)d_in[1]; }
    else                         { s = (const float*)d_in[1]; etas = (const float*)d_in[0]; }
    float* out = (float*)d_out;

    fused_unpool_kernel<<<64u * 128u, 256>>>(etas, s, out);
}

// round 9
// speedup vs baseline: 1.0060x; 1.0060x over previous
#include <cuda_runtime.h>
#include <cstdint>

// Problem constants (fixed by setup_inputs): B=32, C=64, n=128, m=128, P=4.

// ---------------------------------------------------------------------------
// JAX partitionable threefry stream, key = jax.random.key(42) -> (k1,k2)=(0,42).
// Element i: (o0,o1) = threefry2x32((0,42), (i>>32, i&0xffffffff)) ; bits = o0^o1
// ---------------------------------------------------------------------------
__device__ __forceinline__ uint32_t threefry_bits(uint32_t i) {
    const uint32_t ks0 = 0u;
    const uint32_t ks1 = 42u;
    const uint32_t ks2 = 0x1BD11BDAu ^ ks0 ^ ks1;   // 0x1BD11BF0
    uint32_t x0 = 0u + ks0;      // counter hi word + ks0
    uint32_t x1 = i  + ks1;      // counter lo word + ks1
#define TF_RND(r) { x0 += x1; x1 = __funnelshift_l(x1, x1, (r)); x1 ^= x0; }
    TF_RND(13) TF_RND(15) TF_RND(26) TF_RND(6)
    x0 += ks1; x1 += ks2 + 1u;
    TF_RND(17) TF_RND(29) TF_RND(16) TF_RND(24)
    x0 += ks2; x1 += ks0 + 2u;
    TF_RND(13) TF_RND(15) TF_RND(26) TF_RND(6)
    x0 += ks0; x1 += ks1 + 3u;
    TF_RND(17) TF_RND(29) TF_RND(16) TF_RND(24)
    x0 += ks1; x1 += ks2 + 4u;
    TF_RND(13) TF_RND(15) TF_RND(26) TF_RND(6)
    x0 += ks2; x1 += ks0 + 5u;
#undef TF_RND
    return x0 ^ x1;
}

// JAX uniform(minval=tiny, maxval=1) + gumbel, reproduced op-for-op in f32.
__device__ __forceinline__ float bits_to_gumbel(uint32_t b) {
    const float tiny = 1.17549435e-38f;            // jnp.finfo(f32).tiny
    float f = __uint_as_float((b >> 9) | 0x3f800000u) - 1.0f;  // [0,1)
    float u = fmaxf(tiny, f + tiny);               // (1 - tiny) == 1.0f exactly
    return -logf(-logf(u));
}

// 256-bit streaming store (sm_100+): one dense 32B sector per thread.
__device__ __forceinline__ void stg256_cs(float* p, float4 a, float4 b) {
    asm volatile("st.global.cs.v8.f32 [%0], {%1,%2,%3,%4,%5,%6,%7,%8};"
                 :: "l"(p),
                    "f"(a.x), "f"(a.y), "f"(a.z), "f"(a.w),
                    "f"(b.x), "f"(b.y), "f"(b.z), "f"(b.w)
                 : "memory");
}

// Scatter one s-float4 into two dense 8-float output rows and store.
__device__ __forceinline__ void scatter_store(float* out_row0, float4 sv, uchar4 z) {
    float4 r0a, r0b, r1a, r1b;
    r0a.x = (z.x == 0) ? sv.x : 0.0f;  r0a.y = (z.x == 1) ? sv.x : 0.0f;
    r0a.z = (z.y == 0) ? sv.y : 0.0f;  r0a.w = (z.y == 1) ? sv.y : 0.0f;
    r0b.x = (z.z == 0) ? sv.z : 0.0f;  r0b.y = (z.z == 1) ? sv.z : 0.0f;
    r0b.z = (z.w == 0) ? sv.w : 0.0f;  r0b.w = (z.w == 1) ? sv.w : 0.0f;
    r1a.x = (z.x == 2) ? sv.x : 0.0f;  r1a.y = (z.x == 3) ? sv.x : 0.0f;
    r1a.z = (z.y == 2) ? sv.y : 0.0f;  r1a.w = (z.y == 3) ? sv.y : 0.0f;
    r1b.x = (z.z == 2) ? sv.z : 0.0f;  r1b.y = (z.z == 3) ? sv.z : 0.0f;
    r1b.z = (z.w == 2) ? sv.w : 0.0f;  r1b.w = (z.w == 3) ? sv.w : 0.0f;
    stg256_cs(out_row0,        r0a, r0b);          // row 2i
    stg256_cs(out_row0 + 256u, r1a, r1b);          // row 2i+1
}

// ---------------------------------------------------------------------------
// Fused kernel. One block per (c, i) tile.
//   Entry:   issue the first two s-loads (independent of zeta) so they fly
//            underneath stage 1's ALU work.
//   stage 1: 256 threads compute the 512 gumbel-perturbed scores for the
//            tile's 128 eta rows (2 each) into smem, argmax -> zeta[128].
//   stage 2: stream all 32 batch slices; remaining loads pipelined, dense
//            256-bit streaming stores.
// ---------------------------------------------------------------------------
__global__ void __launch_bounds__(256, 4) fused_unpool_kernel(
        const float* __restrict__ etas,
        const float* __restrict__ s,
        float* __restrict__ out) {
    __shared__ float vals[128][5];                 // pad 5: conflict-free argmax
    __shared__ __align__(4) unsigned char zsm[128];

    const unsigned c = blockIdx.x >> 7;            // 0..63
    const unsigned i = blockIdx.x & 127u;          // 0..127
    const unsigned t = threadIdx.x;

    // ---- prefetch: first two s slices, in flight during stage 1 ----
    const unsigned j4 = t & 31u;                   // 4-j group 0..31
    const unsigned bl = t >> 5;                    // 0..7
    const float* sp = s   + (((bl * 64u + c) * 128u + i) * 128u) + (j4 << 2);
    float*       op = out + ((bl * 64u + c) * 256u + 2u * i) * 256u + (j4 << 3);
    const unsigned S_STRIDE = 8u * 64u * 16384u;
    const unsigned O_STRIDE = 8u * 64u * 65536u;

    float4 sv0 = __ldcs((const float4*)(sp));
    float4 sv1 = __ldcs((const float4*)(sp + S_STRIDE));

    // ---- stage 1: sample zeta for the 128 rows r = (i*128+j)*64 + c ----
#pragma unroll
    for (int h = 0; h < 2; ++h) {
        unsigned q = t + (unsigned)h * 256u;       // q = j*4 + p, q < 512
        unsigned j = q >> 2;
        unsigned p = q & 3u;
        unsigned ctr = 4u * ((i * 128u + j) * 64u + c) + p;
        uint32_t b = threefry_bits(ctr);
        float e = __ldg(etas + ctr);               // etas[r][p] == etas[4r+p]
        vals[j][p] = logf(fmaxf(e, 1e-30f)) + bits_to_gumbel(b);
    }
    __syncthreads();
    if (t < 128u) {                                // first-max argmax (jnp.argmax)
        float v0 = vals[t][0], v1 = vals[t][1], v2 = vals[t][2], v3 = vals[t][3];
        int zi = 0; float zv = v0;
        if (v1 > zv) { zv = v1; zi = 1; }
        if (v2 > zv) { zv = v2; zi = 2; }
        if (v3 > zv) { zv = v3; zi = 3; }
        zsm[t] = (unsigned char)zi;
    }
    __syncthreads();

    // ---- stage 2: scatter all 32 batch slices ----
    const uchar4 z = *(const uchar4*)&zsm[j4 << 2];

    float4 sv2 = __ldcs((const float4*)(sp + 2u * S_STRIDE));
    scatter_store(op, sv0, z);
    float4 sv3 = __ldcs((const float4*)(sp + 3u * S_STRIDE));
    scatter_store(op + O_STRIDE, sv1, z);
    scatter_store(op + 2u * O_STRIDE, sv2, z);
    scatter_store(op + 3u * O_STRIDE, sv3, z);
}

extern "C" void kernel_launch(void* const* d_in, const int* in_sizes, int n_in,
                              void* d_out, int out_size) {
    // s has 33,554,432 elems; etas 4,194,304. Select by size for robustness.
    const float* s;
    const float* etas;
    if (in_sizes[0] == 33554432) { s = (const float*)d_in[0]; etas = (const float*)d_in[1]; }
    else                         { s = (const float*)d_in[1]; etas = (const float*)d_in[0]; }
    float* out = (float*)d_out;

    fused_unpool_kernel<<<64u * 128u, 256>>>(etas, s, out);
}